// round 11
// baseline (speedup 1.0000x reference)
#include <cuda_runtime.h>
#include <cuda_bf16.h>
#include <cstdint>

#define BB 4
#define SS 1024
#define DDIM 512
#define HH 8
#define DH 64
#define RP (2*SS-1)   // 2047

// Output layout (tuple concatenated, float32):
//   out      [B,S,D]      @ 0
//   attn     [B,H,S,S]    @ OFF_ATTN
//   content  [B,H,S,S]    @ OFF_CONTENT
//   pos      [B,H,S,S]    @ OFF_POS   (already relative-shifted)
#define N_OUT  ((size_t)BB*SS*DDIM)
#define N_SC   ((size_t)BB*HH*SS*SS)
#define OFF_ATTN     (N_OUT)
#define OFF_CONTENT  (N_OUT + N_SC)
#define OFF_POS      (N_OUT + 2*N_SC)

// Scratch (allocation-free: device globals)
__device__ float g_q[BB*SS*DDIM];
__device__ float g_k[BB*SS*DDIM];
__device__ float g_v[BB*SS*DDIM];
__device__ float g_oh[BB*SS*DDIM];
__device__ float g_rel[RP*DH];

// Packed f32x2 FMA (Blackwell FFMA2): d = a*b + d, elementwise on 2 lanes.
__device__ __forceinline__ void ffma2(float2& d, const float2& a, const float2& b) {
    asm("fma.rn.f32x2 %0, %1, %2, %0;"
        : "+l"(reinterpret_cast<unsigned long long&>(d))
        : "l"(reinterpret_cast<const unsigned long long&>(a)),
          "l"(reinterpret_cast<const unsigned long long&>(b)));
}

__device__ __forceinline__ uint32_t smem_u32(const void* p) {
    uint32_t a;
    asm("{ .reg .u64 t; cvta.to.shared.u64 t, %1; cvt.u32.u64 %0, t; }"
        : "=r"(a) : "l"(p));
    return a;
}

// split 4 floats into bf16 hi/lo, packed 4-wide into u64 (k-order preserved)
__device__ __forceinline__ void split4(float4 v, unsigned long long& hi, unsigned long long& lo) {
    __nv_bfloat16 h0 = __float2bfloat16(v.x);
    __nv_bfloat16 h1 = __float2bfloat16(v.y);
    __nv_bfloat16 h2 = __float2bfloat16(v.z);
    __nv_bfloat16 h3 = __float2bfloat16(v.w);
    __nv_bfloat16 l0 = __float2bfloat16(v.x - __bfloat162float(h0));
    __nv_bfloat16 l1 = __float2bfloat16(v.y - __bfloat162float(h1));
    __nv_bfloat16 l2 = __float2bfloat16(v.z - __bfloat162float(h2));
    __nv_bfloat16 l3 = __float2bfloat16(v.w - __bfloat162float(h3));
    hi = (unsigned long long)__bfloat16_as_ushort(h0)
       | ((unsigned long long)__bfloat16_as_ushort(h1) << 16)
       | ((unsigned long long)__bfloat16_as_ushort(h2) << 32)
       | ((unsigned long long)__bfloat16_as_ushort(h3) << 48);
    lo = (unsigned long long)__bfloat16_as_ushort(l0)
       | ((unsigned long long)__bfloat16_as_ushort(l1) << 16)
       | ((unsigned long long)__bfloat16_as_ushort(l2) << 32)
       | ((unsigned long long)__bfloat16_as_ushort(l3) << 48);
}

#define LDSM_X4(d0, d1, d2, d3, addr) \
    asm volatile("ldmatrix.sync.aligned.m8n8.x4.shared.b16 {%0,%1,%2,%3}, [%4];" \
        : "=r"(d0), "=r"(d1), "=r"(d2), "=r"(d3) : "r"(addr))

#define MMA16816(c, a, b0_, b1_) \
    asm volatile("mma.sync.aligned.m16n8k16.row.col.f32.bf16.bf16.f32 " \
        "{%0,%1,%2,%3}, {%4,%5,%6,%7}, {%8,%9}, {%0,%1,%2,%3};" \
        : "+f"((c)[0]), "+f"((c)[1]), "+f"((c)[2]), "+f"((c)[3]) \
        : "r"((a)[0]), "r"((a)[1]), "r"((a)[2]), "r"((a)[3]), "r"(b0_), "r"(b1_))

// smem byte offsets for content kernel (bf16 tiles, 128 rows x 64 k, 128B/row)
#define CQHI 0
#define CQLO 16384
#define CKHI 32768
#define CKLO 49152
#define C_SMEM_TOTAL 65536

// ---------------------------------------------------------------------------
// content[z,s,t] = sum_d q[z,s,d]*k[z,t,d]  via mma.sync bf16-split (3 passes:
// hh + hl + lh; lo*lo dropped). Block = 128x128 tile, 8 warps (2m x 4n of
// 64x32 warp tiles). XOR-swizzled smem rows -> conflict-free ldmatrix.
// ---------------------------------------------------------------------------
__global__ void __launch_bounds__(256)
content_kernel(const float* __restrict__ Qp, const float* __restrict__ Kp,
               float* __restrict__ outc) {
    extern __shared__ char smc[];
    const uint32_t sbase = smem_u32(smc);

    const int z = blockIdx.z;
    const int b = z >> 3, h = z & 7;
    const int s0 = blockIdx.y * 128, t0 = blockIdx.x * 128;
    const int tid = threadIdx.x, lane = tid & 31, wid = tid >> 5;
    const int wm = wid & 1, wn = wid >> 1;   // warp tile: rows wm*64.., cols wn*32..

    // ---- load fp32, split to bf16 hi/lo, store swizzled (8B stores) ----
    // physical offset: row*128 + ((chunk ^ (row&7))<<4) + (k&4)*2
#pragma unroll
    for (int it = 0; it < 8; it++) {
        int idx = tid + 256 * it;
        int row = idx >> 4, cg = (idx & 15) << 2;
        uint32_t off = (uint32_t)(row * 128 + ((((cg >> 3)) ^ (row & 7)) << 4) + ((cg & 4) << 1));
        float4 qv = *(const float4*)&Qp[((size_t)(b * SS + s0 + row)) * DDIM + h * DH + cg];
        float4 kv = *(const float4*)&Kp[((size_t)(b * SS + t0 + row)) * DDIM + h * DH + cg];
        unsigned long long hi, lo;
        split4(qv, hi, lo);
        *(unsigned long long*)(smc + CQHI + off) = hi;
        *(unsigned long long*)(smc + CQLO + off) = lo;
        split4(kv, hi, lo);
        *(unsigned long long*)(smc + CKHI + off) = hi;
        *(unsigned long long*)(smc + CKLO + off) = lo;
    }
    __syncthreads();

    float acc[4][4][4];   // [mt][nt][c0..c3]
#pragma unroll
    for (int mt = 0; mt < 4; mt++)
#pragma unroll
        for (int nt = 0; nt < 4; nt++)
#pragma unroll
            for (int c = 0; c < 4; c++) acc[mt][nt][c] = 0.f;

    // ldmatrix lane->address components
    const int ra = (lane & 7) + ((lane >> 3) & 1) * 8;  // A: row within m16
    const int ca = (lane >> 4) & 1;                     // A: k-chunk add
    const int rb = (lane & 7) + ((lane >> 4) & 1) * 8;  // B: row within n16
    const int cbk = (lane >> 3) & 1;                    // B: k-chunk add

#pragma unroll
    for (int pass = 0; pass < 3; pass++) {
        const uint32_t abase = sbase + ((pass == 2) ? CQLO : CQHI);
        const uint32_t bbase = sbase + ((pass == 1) ? CKLO : CKHI);
#pragma unroll
        for (int k0 = 0; k0 < 64; k0 += 16) {
            const int kc = k0 >> 3;
            uint32_t a[4][4];
#pragma unroll
            for (int mt = 0; mt < 4; mt++) {
                int row = wm * 64 + mt * 16 + ra;
                int chunk = kc + ca;
                uint32_t addr = abase + row * 128 + (((chunk ^ (row & 7))) << 4);
                LDSM_X4(a[mt][0], a[mt][1], a[mt][2], a[mt][3], addr);
            }
            uint32_t bf[2][4];
#pragma unroll
            for (int nt2 = 0; nt2 < 2; nt2++) {
                int row = wn * 32 + nt2 * 16 + rb;
                int chunk = kc + cbk;
                uint32_t addr = bbase + row * 128 + (((chunk ^ (row & 7))) << 4);
                LDSM_X4(bf[nt2][0], bf[nt2][1], bf[nt2][2], bf[nt2][3], addr);
            }
#pragma unroll
            for (int mt = 0; mt < 4; mt++)
#pragma unroll
                for (int nt = 0; nt < 4; nt++)
                    MMA16816(acc[mt][nt], a[mt],
                             bf[nt >> 1][(nt & 1) * 2], bf[nt >> 1][(nt & 1) * 2 + 1]);
        }
    }

    // ---- epilogue: c0:(r,c) c1:(r,c+1) c2:(r+8,c) c3:(r+8,c+1) ----
#pragma unroll
    for (int mt = 0; mt < 4; mt++)
#pragma unroll
        for (int nt = 0; nt < 4; nt++) {
            int r = s0 + wm * 64 + mt * 16 + (lane >> 2);
            int c = t0 + wn * 32 + nt * 8 + (lane & 3) * 2;
            size_t o = ((size_t)z * SS + r) * SS + c;
            *(float2*)&outc[o] = make_float2(acc[mt][nt][0], acc[mt][nt][1]);
            *(float2*)&outc[o + 8 * SS] = make_float2(acc[mt][nt][2], acc[mt][nt][3]);
        }
}

// ---------------------------------------------------------------------------
// C[M,N] = A[M,K] @ W[N,K]^T + bias     (M=4096, N=512, K=512)
// 128x128 block tile, 256 threads, 8x8 micro-tile, f32x2 packed.
// ---------------------------------------------------------------------------
__global__ void __launch_bounds__(256, 1)
proj_gemm(const float* __restrict__ A, const float* __restrict__ W,
          const float* __restrict__ bias, float* __restrict__ C) {
    const int K = DDIM, N = DDIM;
    __shared__ float As[128][20];
    __shared__ float Ws[128][20];
    const int tid = threadIdx.x;
    const int tx = tid & 15, ty = tid >> 4;
    const int m0 = blockIdx.y * 128, n0 = blockIdx.x * 128;

    float2 acc[8][8];
#pragma unroll
    for (int i = 0; i < 8; i++)
#pragma unroll
        for (int j = 0; j < 8; j++) acc[i][j] = make_float2(0.f, 0.f);

    float4 pa[2], pw[2];
#pragma unroll
    for (int it = 0; it < 2; it++) {
        int idx = tid + 256 * it, row = idx >> 2, q = (idx & 3) << 2;
        pa[it] = *(const float4*)&A[(size_t)(m0 + row) * K + q];
        pw[it] = *(const float4*)&W[(size_t)(n0 + row) * K + q];
    }

    for (int k0 = 0; k0 < K; k0 += 16) {
#pragma unroll
        for (int it = 0; it < 2; it++) {
            int idx = tid + 256 * it, row = idx >> 2, q = (idx & 3) << 2;
            *(float4*)&As[row][q] = pa[it];
            *(float4*)&Ws[row][q] = pw[it];
        }
        __syncthreads();
        if (k0 + 16 < K) {
#pragma unroll
            for (int it = 0; it < 2; it++) {
                int idx = tid + 256 * it, row = idx >> 2, q = (idx & 3) << 2;
                pa[it] = *(const float4*)&A[(size_t)(m0 + row) * K + k0 + 16 + q];
                pw[it] = *(const float4*)&W[(size_t)(n0 + row) * K + k0 + 16 + q];
            }
        }
#pragma unroll
        for (int kk0 = 0; kk0 < 16; kk0 += 4) {
            float4 af[8];
#pragma unroll
            for (int i = 0; i < 8; i++) af[i] = *(const float4*)&As[ty + 16*i][kk0];
#pragma unroll
            for (int j = 0; j < 8; j++) {
                float4 wf = *(const float4*)&Ws[tx + 16*j][kk0];
                float2 wa = make_float2(wf.x, wf.y), wb = make_float2(wf.z, wf.w);
#pragma unroll
                for (int i = 0; i < 8; i++) {
                    float2 aa = make_float2(af[i].x, af[i].y);
                    float2 ab = make_float2(af[i].z, af[i].w);
                    ffma2(acc[i][j], aa, wa);
                    ffma2(acc[i][j], ab, wb);
                }
            }
        }
        __syncthreads();
    }
#pragma unroll
    for (int i = 0; i < 8; i++)
#pragma unroll
        for (int j = 0; j < 8; j++) {
            int m = m0 + ty + 16*i, n = n0 + tx + 16*j;
            C[(size_t)m * N + n] = acc[i][j].x + acc[i][j].y + bias[n];
        }
}

// ---------------------------------------------------------------------------
// rel[r,n] = sum_k pos_emb[r,k] * Wp[n,k] + bp[n]   (r<2047, n,k<64)
// ---------------------------------------------------------------------------
__global__ void rel_proj(const float* __restrict__ pos_emb, const float* __restrict__ Wp,
                         const float* __restrict__ bp, float* __restrict__ rel) {
    __shared__ float pe[DH];
    __shared__ float wps[DH][DH + 1];
    const int r = blockIdx.x;
    const int tid = threadIdx.x;
    pe[tid] = pos_emb[(size_t)r * DH + tid];
#pragma unroll
    for (int j = 0; j < DH; j++) wps[j][tid] = Wp[(size_t)j * DH + tid];
    __syncthreads();
    float acc = bp[tid];
#pragma unroll 8
    for (int k = 0; k < DH; k++) acc += pe[k] * wps[tid][k];
    rel[(size_t)r * DH + tid] = acc;
}

// ---------------------------------------------------------------------------
// pos[z,s,t] = sum_d q[z,s,d]*rel[t-s+S-1,d]   (skew collapsed)
// Block = 128x128 tile; rel window 255 rows. 8x8 micro, f32x2 packed.
// ---------------------------------------------------------------------------
__global__ void __launch_bounds__(256, 1)
pos_kernel(const float* __restrict__ Qp, const float* __restrict__ rel,
           float* __restrict__ outp) {
    extern __shared__ float sm[];
    float (*qs)[68] = (float(*)[68])sm;
    float (*rs)[68] = (float(*)[68])(sm + 128 * 68);

    const int z = blockIdx.z;
    const int b = z >> 3, h = z & 7;
    const int s0 = blockIdx.y * 128, t0 = blockIdx.x * 128;
    const int tid = threadIdx.x, tx = tid & 15, ty = tid >> 4;

#pragma unroll
    for (int it = 0; it < 8; it++) {
        int idx = tid + 256 * it, row = idx >> 4, c = (idx & 15) << 2;
        *(float4*)&qs[row][c] =
            *(const float4*)&Qp[((size_t)(b * SS + s0 + row)) * DDIM + h * DH + c];
    }
    const int baser = t0 - s0 + SS - 1 - 127;
    for (int idx = tid; idx < 255 * 16; idx += 256) {
        int row = idx >> 4, c = (idx & 15) << 2;
        *(float4*)&rs[row][c] = *(const float4*)&rel[(size_t)(baser + row) * DH + c];
    }
    __syncthreads();

    float2 acc[8][8];
#pragma unroll
    for (int i = 0; i < 8; i++)
#pragma unroll
        for (int j = 0; j < 8; j++) acc[i][j] = make_float2(0.f, 0.f);

    const int rbase = tx - ty + 15;
#pragma unroll 4
    for (int d0 = 0; d0 < 64; d0 += 4) {
        float4 af[8];
#pragma unroll
        for (int i = 0; i < 8; i++) af[i] = *(const float4*)&qs[ty + 16*i][d0];
#pragma unroll
        for (int m = 0; m < 15; m++) {
            float4 r4 = *(const float4*)&rs[rbase + 16*m][d0];
            float2 ra = make_float2(r4.x, r4.y), rb = make_float2(r4.z, r4.w);
#pragma unroll
            for (int i = 0; i < 8; i++) {
                int j = m - 7 + i;
                if (j >= 0 && j < 8) {
                    float2 aa = make_float2(af[i].x, af[i].y);
                    float2 ab = make_float2(af[i].z, af[i].w);
                    ffma2(acc[i][j], aa, ra);
                    ffma2(acc[i][j], ab, rb);
                }
            }
        }
    }

#pragma unroll
    for (int i = 0; i < 8; i++)
#pragma unroll
        for (int j = 0; j < 8; j++) {
            int s = s0 + ty + 16*i, t = t0 + tx + 16*j;
            outp[((size_t)z * SS + s) * SS + t] = acc[i][j].x + acc[i][j].y;
        }
}

// ---------------------------------------------------------------------------
// Softmax over rows of (content + pos) / sqrt(D). One block per row, float4.
// ---------------------------------------------------------------------------
__global__ void softmax_kernel(const float* __restrict__ outc, const float* __restrict__ outp,
                               float* __restrict__ attn) {
    const size_t row = blockIdx.x;
    const float* c = outc + row * SS;
    const float* p = outp + row * SS;
    const int tid = threadIdx.x;
    const int lane = tid & 31, wid = tid >> 5;
    const float scale = 0.044194173824159216f; // 1/sqrt(512)

    float4 c4 = *(const float4*)&c[4 * tid];
    float4 p4 = *(const float4*)&p[4 * tid];
    float v[4];
    v[0] = (c4.x + p4.x) * scale; v[1] = (c4.y + p4.y) * scale;
    v[2] = (c4.z + p4.z) * scale; v[3] = (c4.w + p4.w) * scale;
    float m = fmaxf(fmaxf(v[0], v[1]), fmaxf(v[2], v[3]));
#pragma unroll
    for (int o = 16; o > 0; o >>= 1) m = fmaxf(m, __shfl_xor_sync(0xffffffffu, m, o));
    __shared__ float redm[8], reds[8];
    if (lane == 0) redm[wid] = m;
    __syncthreads();
    if (tid == 0) {
        float mm = redm[0];
#pragma unroll
        for (int i = 1; i < 8; i++) mm = fmaxf(mm, redm[i]);
        redm[0] = mm;
    }
    __syncthreads();
    m = redm[0];

    float s = 0.f;
#pragma unroll
    for (int u = 0; u < 4; u++) { v[u] = __expf(v[u] - m); s += v[u]; }
#pragma unroll
    for (int o = 16; o > 0; o >>= 1) s += __shfl_xor_sync(0xffffffffu, s, o);
    if (lane == 0) reds[wid] = s;
    __syncthreads();
    if (tid == 0) {
        float ss = 0.f;
#pragma unroll
        for (int i = 0; i < 8; i++) ss += reds[i];
        reds[0] = ss;
    }
    __syncthreads();
    const float inv = 1.f / reds[0];
    float4 o4 = make_float4(v[0] * inv, v[1] * inv, v[2] * inv, v[3] * inv);
    *(float4*)&attn[row * SS + 4 * tid] = o4;
}

// ---------------------------------------------------------------------------
// out_h[b,s,h*64+d] = sum_t attn[z,s,t] * v[b,t,h*64+d]
// Block = 128 s-rows x dh=64 for one z. 8x4 micro, f32x2 packed.
// ---------------------------------------------------------------------------
__global__ void __launch_bounds__(256, 2)
av_kernel(const float* __restrict__ attn, const float* __restrict__ Vp,
          float* __restrict__ Oh) {
    extern __shared__ float sm[];
    float (*as_)[68] = (float(*)[68])sm;              // [128 s][t]
    float (*vsT)[68] = (float(*)[68])(sm + 128 * 68); // [64 d][t]
    const int z = blockIdx.y;
    const int b = z >> 3, h = z & 7;
    const int s0 = blockIdx.x * 128;
    const int tid = threadIdx.x, tx = tid & 15, ty = tid >> 4;

    float2 acc[8][4];
#pragma unroll
    for (int i = 0; i < 8; i++)
#pragma unroll
        for (int j = 0; j < 4; j++) acc[i][j] = make_float2(0.f, 0.f);

    for (int t0 = 0; t0 < SS; t0 += 64) {
#pragma unroll
        for (int it = 0; it < 8; it++) {
            int idx = tid + 256 * it, row = idx >> 4, c = (idx & 15) << 2;
            *(float4*)&as_[row][c] =
                *(const float4*)&attn[((size_t)z * SS + s0 + row) * SS + t0 + c];
        }
#pragma unroll
        for (int it = 0; it < 4; it++) {
            int idx = tid + 256 * it;
            int trow = idx & 63, cb = (idx >> 6) << 2;
            float4 v4 = *(const float4*)&Vp[((size_t)(b * SS + t0 + trow)) * DDIM + h * DH + cb];
            vsT[cb + 0][trow] = v4.x;
            vsT[cb + 1][trow] = v4.y;
            vsT[cb + 2][trow] = v4.z;
            vsT[cb + 3][trow] = v4.w;
        }
        __syncthreads();
#pragma unroll 4
        for (int tt0 = 0; tt0 < 64; tt0 += 4) {
            float4 af[8];
#pragma unroll
            for (int i = 0; i < 8; i++) af[i] = *(const float4*)&as_[ty + 16*i][tt0];
#pragma unroll
            for (int j = 0; j < 4; j++) {
                float4 vf = *(const float4*)&vsT[tx + 16*j][tt0];
                float2 va = make_float2(vf.x, vf.y), vb = make_float2(vf.z, vf.w);
#pragma unroll
                for (int i = 0; i < 8; i++) {
                    float2 aa = make_float2(af[i].x, af[i].y);
                    float2 ab = make_float2(af[i].z, af[i].w);
                    ffma2(acc[i][j], aa, va);
                    ffma2(acc[i][j], ab, vb);
                }
            }
        }
        __syncthreads();
    }
#pragma unroll
    for (int i = 0; i < 8; i++)
#pragma unroll
        for (int j = 0; j < 4; j++)
            Oh[((size_t)(b * SS + s0 + ty + 16*i)) * DDIM + h * DH + tx + 16*j] =
                acc[i][j].x + acc[i][j].y;
}

// ---------------------------------------------------------------------------
extern "C" void kernel_launch(void* const* d_in, const int* in_sizes, int n_in,
                              void* d_out, int out_size) {
    const float* query   = (const float*)d_in[0];
    const float* key     = (const float*)d_in[1];
    const float* value   = (const float*)d_in[2];
    const float* pos_emb = (const float*)d_in[3];
    const float* Wq = (const float*)d_in[4];
    const float* bq = (const float*)d_in[5];
    const float* Wk = (const float*)d_in[6];
    const float* bk = (const float*)d_in[7];
    const float* Wv = (const float*)d_in[8];
    const float* bv = (const float*)d_in[9];
    const float* Wo = (const float*)d_in[10];
    const float* bo = (const float*)d_in[11];
    const float* Wp = (const float*)d_in[12];
    const float* bp = (const float*)d_in[13];
    float* out = (float*)d_out;

    float *gq, *gk, *gv, *goh, *grel;
    cudaGetSymbolAddress((void**)&gq, g_q);
    cudaGetSymbolAddress((void**)&gk, g_k);
    cudaGetSymbolAddress((void**)&gv, g_v);
    cudaGetSymbolAddress((void**)&goh, g_oh);
    cudaGetSymbolAddress((void**)&grel, g_rel);

    const int pos_smem = (128 + 255) * 68 * (int)sizeof(float);    // 104176
    const int av_smem  = (128 + 64) * 68 * (int)sizeof(float);     // 52224
    cudaFuncSetAttribute(content_kernel, cudaFuncAttributeMaxDynamicSharedMemorySize, C_SMEM_TOTAL);
    cudaFuncSetAttribute(pos_kernel,     cudaFuncAttributeMaxDynamicSharedMemorySize, pos_smem);
    cudaFuncSetAttribute(av_kernel,      cudaFuncAttributeMaxDynamicSharedMemorySize, av_smem);

    dim3 gproj(DDIM / 128, (BB * SS) / 128);   // (4, 32)
    // Launch order puts content_kernel at index 3 (the slot ncu has been
    // profiling) while preserving dependencies.
    proj_gemm<<<gproj, 256>>>(query, Wq, bq, gq);                       // 0
    proj_gemm<<<gproj, 256>>>(key,   Wk, bk, gk);                       // 1
    rel_proj<<<RP, DH>>>(pos_emb, Wp, bp, grel);                        // 2
    content_kernel<<<dim3(SS / 128, SS / 128, BB * HH), 256, C_SMEM_TOTAL>>>(
        gq, gk, out + OFF_CONTENT);                                     // 3
    proj_gemm<<<gproj, 256>>>(value, Wv, bv, gv);                       // 4
    pos_kernel<<<dim3(SS / 128, SS / 128, BB * HH), 256, pos_smem>>>(
        gq, grel, out + OFF_POS);                                       // 5
    softmax_kernel<<<BB * HH * SS, 256>>>(out + OFF_CONTENT, out + OFF_POS, out + OFF_ATTN); // 6
    av_kernel<<<dim3(SS / 128, BB * HH), 256, av_smem>>>(out + OFF_ATTN, gv, goh);           // 7
    proj_gemm<<<gproj, 256>>>(goh, Wo, bo, out);                        // 8
}

// round 16
// speedup vs baseline: 1.0704x; 1.0704x over previous
#include <cuda_runtime.h>
#include <cuda_bf16.h>
#include <cstdint>

#define BB 4
#define SS 1024
#define DDIM 512
#define HH 8
#define DH 64
#define RP (2*SS-1)   // 2047

#define N_OUT  ((size_t)BB*SS*DDIM)
#define N_SC   ((size_t)BB*HH*SS*SS)
#define OFF_ATTN     (N_OUT)
#define OFF_CONTENT  (N_OUT + N_SC)
#define OFF_POS      (N_OUT + 2*N_SC)

// Scratch (allocation-free: device globals)
__device__ float g_q[BB*SS*DDIM];
__device__ float g_k[BB*SS*DDIM];
__device__ float g_v[BB*SS*DDIM];
__device__ float g_oh[BB*SS*DDIM];
__device__ float g_rel[RP*DH];

// Packed f32x2 FMA (Blackwell FFMA2)
__device__ __forceinline__ void ffma2(float2& d, const float2& a, const float2& b) {
    asm("fma.rn.f32x2 %0, %1, %2, %0;"
        : "+l"(reinterpret_cast<unsigned long long&>(d))
        : "l"(reinterpret_cast<const unsigned long long&>(a)),
          "l"(reinterpret_cast<const unsigned long long&>(b)));
}

__device__ __forceinline__ uint32_t smem_u32(const void* p) {
    uint32_t a;
    asm("{ .reg .u64 t; cvta.to.shared.u64 t, %1; cvt.u32.u64 %0, t; }"
        : "=r"(a) : "l"(p));
    return a;
}

// split 4 floats into bf16 hi/lo, packed 4-wide into u64 (k-order preserved)
__device__ __forceinline__ void split4(float4 v, unsigned long long& hi, unsigned long long& lo) {
    __nv_bfloat16 h0 = __float2bfloat16(v.x);
    __nv_bfloat16 h1 = __float2bfloat16(v.y);
    __nv_bfloat16 h2 = __float2bfloat16(v.z);
    __nv_bfloat16 h3 = __float2bfloat16(v.w);
    __nv_bfloat16 l0 = __float2bfloat16(v.x - __bfloat162float(h0));
    __nv_bfloat16 l1 = __float2bfloat16(v.y - __bfloat162float(h1));
    __nv_bfloat16 l2 = __float2bfloat16(v.z - __bfloat162float(h2));
    __nv_bfloat16 l3 = __float2bfloat16(v.w - __bfloat162float(h3));
    hi = (unsigned long long)__bfloat16_as_ushort(h0)
       | ((unsigned long long)__bfloat16_as_ushort(h1) << 16)
       | ((unsigned long long)__bfloat16_as_ushort(h2) << 32)
       | ((unsigned long long)__bfloat16_as_ushort(h3) << 48);
    lo = (unsigned long long)__bfloat16_as_ushort(l0)
       | ((unsigned long long)__bfloat16_as_ushort(l1) << 16)
       | ((unsigned long long)__bfloat16_as_ushort(l2) << 32)
       | ((unsigned long long)__bfloat16_as_ushort(l3) << 48);
}

#define LDSM_X4(d0, d1, d2, d3, addr) \
    asm volatile("ldmatrix.sync.aligned.m8n8.x4.shared.b16 {%0,%1,%2,%3}, [%4];" \
        : "=r"(d0), "=r"(d1), "=r"(d2), "=r"(d3) : "r"(addr))

#define MMA16816(c, a, b0_, b1_) \
    asm volatile("mma.sync.aligned.m16n8k16.row.col.f32.bf16.bf16.f32 " \
        "{%0,%1,%2,%3}, {%4,%5,%6,%7}, {%8,%9}, {%0,%1,%2,%3};" \
        : "+f"((c)[0]), "+f"((c)[1]), "+f"((c)[2]), "+f"((c)[3]) \
        : "r"((a)[0]), "r"((a)[1]), "r"((a)[2]), "r"((a)[3]), "r"(b0_), "r"(b1_))

// smem byte offsets (bf16 tiles, 128 rows x 64 k, 128B/row, XOR swizzle)
#define TAHI 0
#define TALO 16384
#define TBHI 32768
#define TBLO 49152
#define T_SMEM_TOTAL 65536

// ---------------------------------------------------------------------------
// Shared mma core: acc[4][4][4] += A(128x64 in TAHI/TALO) * B(128x64)^T
// 3-pass bf16 split (hh + hl + lh); fragments hoisted to registers per k0.
// 8 warps: wm = wid&1 (rows wm*64+mt*16), wn = wid>>1 (cols wn*32+nt*8).
// ---------------------------------------------------------------------------
__device__ __forceinline__ void mma_core_128x128(const uint32_t sbase, int lane,
                                                 int wm, int wn, float acc[4][4][4]) {
    const int ra = lane & 15;                      // A row within m16
    const int ca = lane >> 4;                      // A k-chunk add
    const int rb = (lane & 7) + ((lane >> 4) & 1) * 8;  // B row within n16
    const int cbk = (lane >> 3) & 1;               // B k-chunk add

#pragma unroll
    for (int k0 = 0; k0 < 64; k0 += 16) {
        const int kc = k0 >> 3;
        uint32_t ahi[4][4], alo[4][4], bhi[2][4], blo[2][4];
#pragma unroll
        for (int mt = 0; mt < 4; mt++) {
            int row = wm * 64 + mt * 16 + ra;
            int chunk = kc + ca;
            uint32_t off = (uint32_t)(row * 128 + ((chunk ^ (row & 7)) << 4));
            LDSM_X4(ahi[mt][0], ahi[mt][1], ahi[mt][2], ahi[mt][3], sbase + TAHI + off);
            LDSM_X4(alo[mt][0], alo[mt][1], alo[mt][2], alo[mt][3], sbase + TALO + off);
        }
#pragma unroll
        for (int nt2 = 0; nt2 < 2; nt2++) {
            int row = wn * 32 + nt2 * 16 + rb;
            int chunk = kc + cbk;
            uint32_t off = (uint32_t)(row * 128 + ((chunk ^ (row & 7)) << 4));
            LDSM_X4(bhi[nt2][0], bhi[nt2][1], bhi[nt2][2], bhi[nt2][3], sbase + TBHI + off);
            LDSM_X4(blo[nt2][0], blo[nt2][1], blo[nt2][2], blo[nt2][3], sbase + TBLO + off);
        }
        // hh
#pragma unroll
        for (int mt = 0; mt < 4; mt++)
#pragma unroll
            for (int nt = 0; nt < 4; nt++)
                MMA16816(acc[mt][nt], ahi[mt],
                         bhi[nt >> 1][(nt & 1) * 2], bhi[nt >> 1][(nt & 1) * 2 + 1]);
        // hl
#pragma unroll
        for (int mt = 0; mt < 4; mt++)
#pragma unroll
            for (int nt = 0; nt < 4; nt++)
                MMA16816(acc[mt][nt], ahi[mt],
                         blo[nt >> 1][(nt & 1) * 2], blo[nt >> 1][(nt & 1) * 2 + 1]);
        // lh
#pragma unroll
        for (int mt = 0; mt < 4; mt++)
#pragma unroll
            for (int nt = 0; nt < 4; nt++)
                MMA16816(acc[mt][nt], alo[mt],
                         bhi[nt >> 1][(nt & 1) * 2], bhi[nt >> 1][(nt & 1) * 2 + 1]);
    }
}

// ---------------------------------------------------------------------------
// content[z,s,t] = sum_d q[z,s,d]*k[z,t,d]  (mma.sync bf16-split)
// ---------------------------------------------------------------------------
__global__ void __launch_bounds__(256)
content_kernel(const float* __restrict__ Qp, const float* __restrict__ Kp,
               float* __restrict__ outc) {
    extern __shared__ char smc[];
    const uint32_t sbase = smem_u32(smc);

    const int z = blockIdx.z;
    const int b = z >> 3, h = z & 7;
    const int s0 = blockIdx.y * 128, t0 = blockIdx.x * 128;
    const int tid = threadIdx.x, lane = tid & 31, wid = tid >> 5;
    const int wm = wid & 1, wn = wid >> 1;

#pragma unroll
    for (int it = 0; it < 8; it++) {
        int idx = tid + 256 * it;
        int row = idx >> 4, cg = (idx & 15) << 2;
        uint32_t off = (uint32_t)(row * 128 + (((cg >> 3) ^ (row & 7)) << 4) + ((cg & 4) << 1));
        float4 qv = *(const float4*)&Qp[((size_t)(b * SS + s0 + row)) * DDIM + h * DH + cg];
        float4 kv = *(const float4*)&Kp[((size_t)(b * SS + t0 + row)) * DDIM + h * DH + cg];
        unsigned long long hi, lo;
        split4(qv, hi, lo);
        *(unsigned long long*)(smc + TAHI + off) = hi;
        *(unsigned long long*)(smc + TALO + off) = lo;
        split4(kv, hi, lo);
        *(unsigned long long*)(smc + TBHI + off) = hi;
        *(unsigned long long*)(smc + TBLO + off) = lo;
    }
    __syncthreads();

    float acc[4][4][4];
#pragma unroll
    for (int mt = 0; mt < 4; mt++)
#pragma unroll
        for (int nt = 0; nt < 4; nt++)
#pragma unroll
            for (int c = 0; c < 4; c++) acc[mt][nt][c] = 0.f;

    mma_core_128x128(sbase, lane, wm, wn, acc);

#pragma unroll
    for (int mt = 0; mt < 4; mt++)
#pragma unroll
        for (int nt = 0; nt < 4; nt++) {
            int r = s0 + wm * 64 + mt * 16 + (lane >> 2);
            int c = t0 + wn * 32 + nt * 8 + (lane & 3) * 2;
            size_t o = ((size_t)z * SS + r) * SS + c;
            *(float2*)&outc[o] = make_float2(acc[mt][nt][0], acc[mt][nt][1]);
            *(float2*)&outc[o + 8 * SS] = make_float2(acc[mt][nt][2], acc[mt][nt][3]);
        }
}

// ---------------------------------------------------------------------------
// pos via mma: raw[s,r] = q[s]·rel[r]; skew applied at store: t = r + s - 1023.
// Grid x = 9 r-tiles covering the band for each 128-row s-tile.
// ---------------------------------------------------------------------------
__global__ void __launch_bounds__(256)
pos_mma_kernel(const float* __restrict__ Qp, const float* __restrict__ rel,
               float* __restrict__ outp) {
    extern __shared__ char smc[];
    const uint32_t sbase = smem_u32(smc);

    const int z = blockIdx.z;
    const int b = z >> 3, h = z & 7;
    const int s0 = blockIdx.y * 128;
    const int r0 = (SS - 128 - s0) + blockIdx.x * 128;   // 896 - s0 + rx*128, >= 0
    const int tid = threadIdx.x, lane = tid & 31, wid = tid >> 5;
    const int wm = wid & 1, wn = wid >> 1;

#pragma unroll
    for (int it = 0; it < 8; it++) {
        int idx = tid + 256 * it;
        int row = idx >> 4, cg = (idx & 15) << 2;
        uint32_t off = (uint32_t)(row * 128 + (((cg >> 3) ^ (row & 7)) << 4) + ((cg & 4) << 1));
        float4 qv = *(const float4*)&Qp[((size_t)(b * SS + s0 + row)) * DDIM + h * DH + cg];
        float4 rv = make_float4(0.f, 0.f, 0.f, 0.f);
        if (r0 + row < RP)
            rv = *(const float4*)&rel[(size_t)(r0 + row) * DH + cg];
        unsigned long long hi, lo;
        split4(qv, hi, lo);
        *(unsigned long long*)(smc + TAHI + off) = hi;
        *(unsigned long long*)(smc + TALO + off) = lo;
        split4(rv, hi, lo);
        *(unsigned long long*)(smc + TBHI + off) = hi;
        *(unsigned long long*)(smc + TBLO + off) = lo;
    }
    __syncthreads();

    float acc[4][4][4];
#pragma unroll
    for (int mt = 0; mt < 4; mt++)
#pragma unroll
        for (int nt = 0; nt < 4; nt++)
#pragma unroll
            for (int c = 0; c < 4; c++) acc[mt][nt][c] = 0.f;

    mma_core_128x128(sbase, lane, wm, wn, acc);

    // skewed store: out[s, t] with t = r_global + s_global - (SS-1)
#pragma unroll
    for (int mt = 0; mt < 4; mt++)
#pragma unroll
        for (int nt = 0; nt < 4; nt++) {
            int s = s0 + wm * 64 + mt * 16 + (lane >> 2);
            int rc = r0 + wn * 32 + nt * 8 + (lane & 3) * 2;
            int t = rc + s - (SS - 1);
            float* base = &outp[((size_t)z * SS + s) * SS];
            if ((unsigned)t < SS)       base[t]     = acc[mt][nt][0];
            if ((unsigned)(t + 1) < SS) base[t + 1] = acc[mt][nt][1];
            int t2 = t + 8;   // row s+8 shifts t by +8
            float* base2 = base + (size_t)8 * SS;
            if ((unsigned)t2 < SS)       base2[t2]     = acc[mt][nt][2];
            if ((unsigned)(t2 + 1) < SS) base2[t2 + 1] = acc[mt][nt][3];
        }
}

// ---------------------------------------------------------------------------
// C[M,N] = A[M,K] @ W[N,K]^T + bias  (scalar f32x2, 128x128, 8x8 micro)
// ---------------------------------------------------------------------------
__global__ void __launch_bounds__(256, 1)
proj_gemm(const float* __restrict__ A, const float* __restrict__ W,
          const float* __restrict__ bias, float* __restrict__ C) {
    const int K = DDIM, N = DDIM;
    __shared__ float As[128][20];
    __shared__ float Ws[128][20];
    const int tid = threadIdx.x;
    const int tx = tid & 15, ty = tid >> 4;
    const int m0 = blockIdx.y * 128, n0 = blockIdx.x * 128;

    float2 acc[8][8];
#pragma unroll
    for (int i = 0; i < 8; i++)
#pragma unroll
        for (int j = 0; j < 8; j++) acc[i][j] = make_float2(0.f, 0.f);

    float4 pa[2], pw[2];
#pragma unroll
    for (int it = 0; it < 2; it++) {
        int idx = tid + 256 * it, row = idx >> 2, q = (idx & 3) << 2;
        pa[it] = *(const float4*)&A[(size_t)(m0 + row) * K + q];
        pw[it] = *(const float4*)&W[(size_t)(n0 + row) * K + q];
    }

    for (int k0 = 0; k0 < K; k0 += 16) {
#pragma unroll
        for (int it = 0; it < 2; it++) {
            int idx = tid + 256 * it, row = idx >> 2, q = (idx & 3) << 2;
            *(float4*)&As[row][q] = pa[it];
            *(float4*)&Ws[row][q] = pw[it];
        }
        __syncthreads();
        if (k0 + 16 < K) {
#pragma unroll
            for (int it = 0; it < 2; it++) {
                int idx = tid + 256 * it, row = idx >> 2, q = (idx & 3) << 2;
                pa[it] = *(const float4*)&A[(size_t)(m0 + row) * K + k0 + 16 + q];
                pw[it] = *(const float4*)&W[(size_t)(n0 + row) * K + k0 + 16 + q];
            }
        }
#pragma unroll
        for (int kk0 = 0; kk0 < 16; kk0 += 4) {
            float4 af[8];
#pragma unroll
            for (int i = 0; i < 8; i++) af[i] = *(const float4*)&As[ty + 16*i][kk0];
#pragma unroll
            for (int j = 0; j < 8; j++) {
                float4 wf = *(const float4*)&Ws[tx + 16*j][kk0];
                float2 wa = make_float2(wf.x, wf.y), wb = make_float2(wf.z, wf.w);
#pragma unroll
                for (int i = 0; i < 8; i++) {
                    float2 aa = make_float2(af[i].x, af[i].y);
                    float2 ab = make_float2(af[i].z, af[i].w);
                    ffma2(acc[i][j], aa, wa);
                    ffma2(acc[i][j], ab, wb);
                }
            }
        }
        __syncthreads();
    }
#pragma unroll
    for (int i = 0; i < 8; i++)
#pragma unroll
        for (int j = 0; j < 8; j++) {
            int m = m0 + ty + 16*i, n = n0 + tx + 16*j;
            C[(size_t)m * N + n] = acc[i][j].x + acc[i][j].y + bias[n];
        }
}

// ---------------------------------------------------------------------------
__global__ void rel_proj(const float* __restrict__ pos_emb, const float* __restrict__ Wp,
                         const float* __restrict__ bp, float* __restrict__ rel) {
    __shared__ float pe[DH];
    __shared__ float wps[DH][DH + 1];
    const int r = blockIdx.x;
    const int tid = threadIdx.x;
    pe[tid] = pos_emb[(size_t)r * DH + tid];
#pragma unroll
    for (int j = 0; j < DH; j++) wps[j][tid] = Wp[(size_t)j * DH + tid];
    __syncthreads();
    float acc = bp[tid];
#pragma unroll 8
    for (int k = 0; k < DH; k++) acc += pe[k] * wps[tid][k];
    rel[(size_t)r * DH + tid] = acc;
}

// ---------------------------------------------------------------------------
__global__ void softmax_kernel(const float* __restrict__ outc, const float* __restrict__ outp,
                               float* __restrict__ attn) {
    const size_t row = blockIdx.x;
    const float* c = outc + row * SS;
    const float* p = outp + row * SS;
    const int tid = threadIdx.x;
    const int lane = tid & 31, wid = tid >> 5;
    const float scale = 0.044194173824159216f; // 1/sqrt(512)

    float4 c4 = *(const float4*)&c[4 * tid];
    float4 p4 = *(const float4*)&p[4 * tid];
    float v[4];
    v[0] = (c4.x + p4.x) * scale; v[1] = (c4.y + p4.y) * scale;
    v[2] = (c4.z + p4.z) * scale; v[3] = (c4.w + p4.w) * scale;
    float m = fmaxf(fmaxf(v[0], v[1]), fmaxf(v[2], v[3]));
#pragma unroll
    for (int o = 16; o > 0; o >>= 1) m = fmaxf(m, __shfl_xor_sync(0xffffffffu, m, o));
    __shared__ float redm[8], reds[8];
    if (lane == 0) redm[wid] = m;
    __syncthreads();
    if (tid == 0) {
        float mm = redm[0];
#pragma unroll
        for (int i = 1; i < 8; i++) mm = fmaxf(mm, redm[i]);
        redm[0] = mm;
    }
    __syncthreads();
    m = redm[0];

    float s = 0.f;
#pragma unroll
    for (int u = 0; u < 4; u++) { v[u] = __expf(v[u] - m); s += v[u]; }
#pragma unroll
    for (int o = 16; o > 0; o >>= 1) s += __shfl_xor_sync(0xffffffffu, s, o);
    if (lane == 0) reds[wid] = s;
    __syncthreads();
    if (tid == 0) {
        float ss = 0.f;
#pragma unroll
        for (int i = 0; i < 8; i++) ss += reds[i];
        reds[0] = ss;
    }
    __syncthreads();
    const float inv = 1.f / reds[0];
    float4 o4 = make_float4(v[0] * inv, v[1] * inv, v[2] * inv, v[3] * inv);
    *(float4*)&attn[row * SS + 4 * tid] = o4;
}

// ---------------------------------------------------------------------------
__global__ void __launch_bounds__(256, 2)
av_kernel(const float* __restrict__ attn, const float* __restrict__ Vp,
          float* __restrict__ Oh) {
    extern __shared__ float sm[];
    float (*as_)[68] = (float(*)[68])sm;
    float (*vsT)[68] = (float(*)[68])(sm + 128 * 68);
    const int z = blockIdx.y;
    const int b = z >> 3, h = z & 7;
    const int s0 = blockIdx.x * 128;
    const int tid = threadIdx.x, tx = tid & 15, ty = tid >> 4;

    float2 acc[8][4];
#pragma unroll
    for (int i = 0; i < 8; i++)
#pragma unroll
        for (int j = 0; j < 4; j++) acc[i][j] = make_float2(0.f, 0.f);

    for (int t0 = 0; t0 < SS; t0 += 64) {
#pragma unroll
        for (int it = 0; it < 8; it++) {
            int idx = tid + 256 * it, row = idx >> 4, c = (idx & 15) << 2;
            *(float4*)&as_[row][c] =
                *(const float4*)&attn[((size_t)z * SS + s0 + row) * SS + t0 + c];
        }
#pragma unroll
        for (int it = 0; it < 4; it++) {
            int idx = tid + 256 * it;
            int trow = idx & 63, cb = (idx >> 6) << 2;
            float4 v4 = *(const float4*)&Vp[((size_t)(b * SS + t0 + trow)) * DDIM + h * DH + cb];
            vsT[cb + 0][trow] = v4.x;
            vsT[cb + 1][trow] = v4.y;
            vsT[cb + 2][trow] = v4.z;
            vsT[cb + 3][trow] = v4.w;
        }
        __syncthreads();
#pragma unroll 4
        for (int tt0 = 0; tt0 < 64; tt0 += 4) {
            float4 af[8];
#pragma unroll
            for (int i = 0; i < 8; i++) af[i] = *(const float4*)&as_[ty + 16*i][tt0];
#pragma unroll
            for (int j = 0; j < 4; j++) {
                float4 vf = *(const float4*)&vsT[tx + 16*j][tt0];
                float2 va = make_float2(vf.x, vf.y), vb = make_float2(vf.z, vf.w);
#pragma unroll
                for (int i = 0; i < 8; i++) {
                    float2 aa = make_float2(af[i].x, af[i].y);
                    float2 ab = make_float2(af[i].z, af[i].w);
                    ffma2(acc[i][j], aa, va);
                    ffma2(acc[i][j], ab, vb);
                }
            }
        }
        __syncthreads();
    }
#pragma unroll
    for (int i = 0; i < 8; i++)
#pragma unroll
        for (int j = 0; j < 4; j++)
            Oh[((size_t)(b * SS + s0 + ty + 16*i)) * DDIM + h * DH + tx + 16*j] =
                acc[i][j].x + acc[i][j].y;
}

// ---------------------------------------------------------------------------
extern "C" void kernel_launch(void* const* d_in, const int* in_sizes, int n_in,
                              void* d_out, int out_size) {
    const float* query   = (const float*)d_in[0];
    const float* key     = (const float*)d_in[1];
    const float* value   = (const float*)d_in[2];
    const float* pos_emb = (const float*)d_in[3];
    const float* Wq = (const float*)d_in[4];
    const float* bq = (const float*)d_in[5];
    const float* Wk = (const float*)d_in[6];
    const float* bk = (const float*)d_in[7];
    const float* Wv = (const float*)d_in[8];
    const float* bv = (const float*)d_in[9];
    const float* Wo = (const float*)d_in[10];
    const float* bo = (const float*)d_in[11];
    const float* Wp = (const float*)d_in[12];
    const float* bp = (const float*)d_in[13];
    float* out = (float*)d_out;

    float *gq, *gk, *gv, *goh, *grel;
    cudaGetSymbolAddress((void**)&gq, g_q);
    cudaGetSymbolAddress((void**)&gk, g_k);
    cudaGetSymbolAddress((void**)&gv, g_v);
    cudaGetSymbolAddress((void**)&goh, g_oh);
    cudaGetSymbolAddress((void**)&grel, g_rel);

    const int av_smem = (128 + 64) * 68 * (int)sizeof(float);
    cudaFuncSetAttribute(content_kernel, cudaFuncAttributeMaxDynamicSharedMemorySize, T_SMEM_TOTAL);
    cudaFuncSetAttribute(pos_mma_kernel, cudaFuncAttributeMaxDynamicSharedMemorySize, T_SMEM_TOTAL);
    cudaFuncSetAttribute(av_kernel,      cudaFuncAttributeMaxDynamicSharedMemorySize, av_smem);

    dim3 gproj(DDIM / 128, (BB * SS) / 128);   // (4, 32)
    proj_gemm<<<gproj, 256>>>(query, Wq, bq, gq);                       // 0
    rel_proj<<<RP, DH>>>(pos_emb, Wp, bp, grel);                        // 1
    proj_gemm<<<gproj, 256>>>(key,   Wk, bk, gk);                       // 2
    pos_mma_kernel<<<dim3(9, SS / 128, BB * HH), 256, T_SMEM_TOTAL>>>(
        gq, grel, out + OFF_POS);                                       // 3 (ncu slot)
    content_kernel<<<dim3(SS / 128, SS / 128, BB * HH), 256, T_SMEM_TOTAL>>>(
        gq, gk, out + OFF_CONTENT);                                     // 4
    proj_gemm<<<gproj, 256>>>(value, Wv, bv, gv);                       // 5
    softmax_kernel<<<BB * HH * SS, 256>>>(out + OFF_CONTENT, out + OFF_POS, out + OFF_ATTN); // 6
    av_kernel<<<dim3(SS / 128, BB * HH), 256, av_smem>>>(out + OFF_ATTN, gv, goh);           // 7
    proj_gemm<<<gproj, 256>>>(goh, Wo, bo, out);                        // 8
}

// round 17
// speedup vs baseline: 1.7373x; 1.6231x over previous
#include <cuda_runtime.h>
#include <cuda_bf16.h>
#include <cstdint>

#define BB 4
#define SS 1024
#define DDIM 512
#define HH 8
#define DH 64
#define RP (2*SS-1)   // 2047

#define N_OUT  ((size_t)BB*SS*DDIM)
#define N_SC   ((size_t)BB*HH*SS*SS)
#define OFF_ATTN     (N_OUT)
#define OFF_CONTENT  (N_OUT + N_SC)
#define OFF_POS      (N_OUT + 2*N_SC)

// Scratch (allocation-free: device globals)
__device__ __nv_bfloat16 g_qhi[BB*SS*DDIM];
__device__ __nv_bfloat16 g_qlo[BB*SS*DDIM];
__device__ __nv_bfloat16 g_khi[BB*SS*DDIM];
__device__ __nv_bfloat16 g_klo[BB*SS*DDIM];
__device__ float g_v[BB*SS*DDIM];
__device__ float g_oh[BB*SS*DDIM];
__device__ __nv_bfloat16 g_relhi[RP*DH];
__device__ __nv_bfloat16 g_rello[RP*DH];

// Packed f32x2 FMA (Blackwell FFMA2)
__device__ __forceinline__ void ffma2(float2& d, const float2& a, const float2& b) {
    asm("fma.rn.f32x2 %0, %1, %2, %0;"
        : "+l"(reinterpret_cast<unsigned long long&>(d))
        : "l"(reinterpret_cast<const unsigned long long&>(a)),
          "l"(reinterpret_cast<const unsigned long long&>(b)));
}

__device__ __forceinline__ uint32_t smem_u32(const void* p) {
    uint32_t a;
    asm("{ .reg .u64 t; cvta.to.shared.u64 t, %1; cvt.u32.u64 %0, t; }"
        : "=r"(a) : "l"(p));
    return a;
}

#define LDSM_X4(d0, d1, d2, d3, addr) \
    asm volatile("ldmatrix.sync.aligned.m8n8.x4.shared.b16 {%0,%1,%2,%3}, [%4];" \
        : "=r"(d0), "=r"(d1), "=r"(d2), "=r"(d3) : "r"(addr))

#define MMA16816(c, a, b0_, b1_) \
    asm volatile("mma.sync.aligned.m16n8k16.row.col.f32.bf16.bf16.f32 " \
        "{%0,%1,%2,%3}, {%4,%5,%6,%7}, {%8,%9}, {%0,%1,%2,%3};" \
        : "+f"((c)[0]), "+f"((c)[1]), "+f"((c)[2]), "+f"((c)[3]) \
        : "r"((a)[0]), "r"((a)[1]), "r"((a)[2]), "r"((a)[3]), "r"(b0_), "r"(b1_))

// smem byte offsets (bf16 tiles, 128 rows x 64 k, 128B/row, XOR swizzle)
#define TAHI 0
#define TALO 16384
#define TBHI 32768
#define TBLO 49152
#define T_SMEM_TOTAL 65536

// ---------------------------------------------------------------------------
// mma core: acc[4][4][4] += A(128x64) * B(128x64)^T, 3-pass bf16 split.
// Restructured for low live-register count: B frags (16 regs) persist per k0;
// A frags (8 regs) live only within one mt iteration.
// ---------------------------------------------------------------------------
__device__ __forceinline__ void mma_core_128x128(const uint32_t sbase, int lane,
                                                 int wm, int wn, float acc[4][4][4]) {
    const int ra = lane & 15;              // A row within m16
    const int ca = lane >> 4;              // A k-chunk select
    const int rb = (lane & 7) + ((lane >> 4) & 1) * 8;  // B row within n16
    const int cbk = (lane >> 3) & 1;       // B k-chunk select

#pragma unroll
    for (int k0 = 0; k0 < 64; k0 += 16) {
        const int kc = k0 >> 3;
        uint32_t bhi[2][4], blo[2][4];
#pragma unroll
        for (int nt2 = 0; nt2 < 2; nt2++) {
            int row = wn * 32 + nt2 * 16 + rb;
            int chunk = kc + cbk;
            uint32_t off = (uint32_t)(row * 128 + ((chunk ^ (row & 7)) << 4));
            LDSM_X4(bhi[nt2][0], bhi[nt2][1], bhi[nt2][2], bhi[nt2][3], sbase + TBHI + off);
            LDSM_X4(blo[nt2][0], blo[nt2][1], blo[nt2][2], blo[nt2][3], sbase + TBLO + off);
        }
#pragma unroll
        for (int mt = 0; mt < 4; mt++) {
            int row = wm * 64 + mt * 16 + ra;
            int chunk = kc + ca;
            uint32_t off = (uint32_t)(row * 128 + ((chunk ^ (row & 7)) << 4));
            uint32_t ahi[4], alo[4];
            LDSM_X4(ahi[0], ahi[1], ahi[2], ahi[3], sbase + TAHI + off);
            LDSM_X4(alo[0], alo[1], alo[2], alo[3], sbase + TALO + off);
            // hh (4 independent acc chains)
#pragma unroll
            for (int nt = 0; nt < 4; nt++)
                MMA16816(acc[mt][nt], ahi,
                         bhi[nt >> 1][(nt & 1) * 2], bhi[nt >> 1][(nt & 1) * 2 + 1]);
            // hl
#pragma unroll
            for (int nt = 0; nt < 4; nt++)
                MMA16816(acc[mt][nt], ahi,
                         blo[nt >> 1][(nt & 1) * 2], blo[nt >> 1][(nt & 1) * 2 + 1]);
            // lh
#pragma unroll
            for (int nt = 0; nt < 4; nt++)
                MMA16816(acc[mt][nt], alo,
                         bhi[nt >> 1][(nt & 1) * 2], bhi[nt >> 1][(nt & 1) * 2 + 1]);
        }
    }
}

// ---------------------------------------------------------------------------
// content[z,s,t] = sum_d q[z,s,d]*k[z,t,d]  — pure-copy loader from presplit
// bf16 hi/lo gmem arrays, then mma core. 2 blocks/SM.
// ---------------------------------------------------------------------------
__global__ void __launch_bounds__(256, 2)
content_kernel(const __nv_bfloat16* __restrict__ qhi, const __nv_bfloat16* __restrict__ qlo,
               const __nv_bfloat16* __restrict__ khi, const __nv_bfloat16* __restrict__ klo,
               float* __restrict__ outc) {
    extern __shared__ char smc[];
    const uint32_t sbase = smem_u32(smc);

    const int z = blockIdx.z;
    const int b = z >> 3, h = z & 7;
    const int s0 = blockIdx.y * 128, t0 = blockIdx.x * 128;
    const int tid = threadIdx.x, lane = tid & 31, wid = tid >> 5;
    const int wm = wid & 1, wn = wid >> 1;

#pragma unroll
    for (int it = 0; it < 4; it++) {
        int idx = tid + 256 * it;               // 0..1023 atoms
        int row = idx >> 3, a = idx & 7;
        uint32_t off = (uint32_t)(row * 128 + ((a ^ (row & 7)) << 4));
        size_t gq = ((size_t)(b * SS + s0 + row)) * DDIM + h * DH + a * 8;
        size_t gk = ((size_t)(b * SS + t0 + row)) * DDIM + h * DH + a * 8;
        *(uint4*)(smc + TAHI + off) = *(const uint4*)&qhi[gq];
        *(uint4*)(smc + TALO + off) = *(const uint4*)&qlo[gq];
        *(uint4*)(smc + TBHI + off) = *(const uint4*)&khi[gk];
        *(uint4*)(smc + TBLO + off) = *(const uint4*)&klo[gk];
    }
    __syncthreads();

    float acc[4][4][4];
#pragma unroll
    for (int mt = 0; mt < 4; mt++)
#pragma unroll
        for (int nt = 0; nt < 4; nt++)
#pragma unroll
            for (int c = 0; c < 4; c++) acc[mt][nt][c] = 0.f;

    mma_core_128x128(sbase, lane, wm, wn, acc);

#pragma unroll
    for (int mt = 0; mt < 4; mt++)
#pragma unroll
        for (int nt = 0; nt < 4; nt++) {
            int r = s0 + wm * 64 + mt * 16 + (lane >> 2);
            int c = t0 + wn * 32 + nt * 8 + (lane & 3) * 2;
            size_t o = ((size_t)z * SS + r) * SS + c;
            *(float2*)&outc[o] = make_float2(acc[mt][nt][0], acc[mt][nt][1]);
            *(float2*)&outc[o + 8 * SS] = make_float2(acc[mt][nt][2], acc[mt][nt][3]);
        }
}

// ---------------------------------------------------------------------------
// pos: raw[s,r] = q[s]·rel[r]; skew applied at store (t = r + s - 1023).
// ---------------------------------------------------------------------------
__global__ void __launch_bounds__(256, 2)
pos_mma_kernel(const __nv_bfloat16* __restrict__ qhi, const __nv_bfloat16* __restrict__ qlo,
               const __nv_bfloat16* __restrict__ relhi, const __nv_bfloat16* __restrict__ rello,
               float* __restrict__ outp) {
    extern __shared__ char smc[];
    const uint32_t sbase = smem_u32(smc);

    const int z = blockIdx.z;
    const int b = z >> 3, h = z & 7;
    const int s0 = blockIdx.y * 128;
    const int r0 = (SS - 128 - s0) + blockIdx.x * 128;
    const int tid = threadIdx.x, lane = tid & 31, wid = tid >> 5;
    const int wm = wid & 1, wn = wid >> 1;

    const uint4 z4 = make_uint4(0u, 0u, 0u, 0u);
#pragma unroll
    for (int it = 0; it < 4; it++) {
        int idx = tid + 256 * it;
        int row = idx >> 3, a = idx & 7;
        uint32_t off = (uint32_t)(row * 128 + ((a ^ (row & 7)) << 4));
        size_t gq = ((size_t)(b * SS + s0 + row)) * DDIM + h * DH + a * 8;
        *(uint4*)(smc + TAHI + off) = *(const uint4*)&qhi[gq];
        *(uint4*)(smc + TALO + off) = *(const uint4*)&qlo[gq];
        uint4 rh = z4, rl = z4;
        if (r0 + row < RP) {
            size_t gr = (size_t)(r0 + row) * DH + a * 8;
            rh = *(const uint4*)&relhi[gr];
            rl = *(const uint4*)&rello[gr];
        }
        *(uint4*)(smc + TBHI + off) = rh;
        *(uint4*)(smc + TBLO + off) = rl;
    }
    __syncthreads();

    float acc[4][4][4];
#pragma unroll
    for (int mt = 0; mt < 4; mt++)
#pragma unroll
        for (int nt = 0; nt < 4; nt++)
#pragma unroll
            for (int c = 0; c < 4; c++) acc[mt][nt][c] = 0.f;

    mma_core_128x128(sbase, lane, wm, wn, acc);

#pragma unroll
    for (int mt = 0; mt < 4; mt++)
#pragma unroll
        for (int nt = 0; nt < 4; nt++) {
            int s = s0 + wm * 64 + mt * 16 + (lane >> 2);
            int rc = r0 + wn * 32 + nt * 8 + (lane & 3) * 2;
            int t = rc + s - (SS - 1);
            float* base = &outp[((size_t)z * SS + s) * SS];
            if ((unsigned)t < SS)       base[t]     = acc[mt][nt][0];
            if ((unsigned)(t + 1) < SS) base[t + 1] = acc[mt][nt][1];
            int t2 = t + 8;
            float* base2 = base + (size_t)8 * SS;
            if ((unsigned)t2 < SS)       base2[t2]     = acc[mt][nt][2];
            if ((unsigned)(t2 + 1) < SS) base2[t2 + 1] = acc[mt][nt][3];
        }
}

// ---------------------------------------------------------------------------
// proj GEMM writing fp32 (for v and final out)
// ---------------------------------------------------------------------------
__global__ void __launch_bounds__(256, 1)
proj_gemm(const float* __restrict__ A, const float* __restrict__ W,
          const float* __restrict__ bias, float* __restrict__ C) {
    const int K = DDIM, N = DDIM;
    __shared__ float As[128][20];
    __shared__ float Ws[128][20];
    const int tid = threadIdx.x;
    const int tx = tid & 15, ty = tid >> 4;
    const int m0 = blockIdx.y * 128, n0 = blockIdx.x * 128;

    float2 acc[8][8];
#pragma unroll
    for (int i = 0; i < 8; i++)
#pragma unroll
        for (int j = 0; j < 8; j++) acc[i][j] = make_float2(0.f, 0.f);

    float4 pa[2], pw[2];
#pragma unroll
    for (int it = 0; it < 2; it++) {
        int idx = tid + 256 * it, row = idx >> 2, q = (idx & 3) << 2;
        pa[it] = *(const float4*)&A[(size_t)(m0 + row) * K + q];
        pw[it] = *(const float4*)&W[(size_t)(n0 + row) * K + q];
    }
    for (int k0 = 0; k0 < K; k0 += 16) {
#pragma unroll
        for (int it = 0; it < 2; it++) {
            int idx = tid + 256 * it, row = idx >> 2, q = (idx & 3) << 2;
            *(float4*)&As[row][q] = pa[it];
            *(float4*)&Ws[row][q] = pw[it];
        }
        __syncthreads();
        if (k0 + 16 < K) {
#pragma unroll
            for (int it = 0; it < 2; it++) {
                int idx = tid + 256 * it, row = idx >> 2, q = (idx & 3) << 2;
                pa[it] = *(const float4*)&A[(size_t)(m0 + row) * K + k0 + 16 + q];
                pw[it] = *(const float4*)&W[(size_t)(n0 + row) * K + k0 + 16 + q];
            }
        }
#pragma unroll
        for (int kk0 = 0; kk0 < 16; kk0 += 4) {
            float4 af[8];
#pragma unroll
            for (int i = 0; i < 8; i++) af[i] = *(const float4*)&As[ty + 16*i][kk0];
#pragma unroll
            for (int j = 0; j < 8; j++) {
                float4 wf = *(const float4*)&Ws[tx + 16*j][kk0];
                float2 wa = make_float2(wf.x, wf.y), wb = make_float2(wf.z, wf.w);
#pragma unroll
                for (int i = 0; i < 8; i++) {
                    float2 aa = make_float2(af[i].x, af[i].y);
                    float2 ab = make_float2(af[i].z, af[i].w);
                    ffma2(acc[i][j], aa, wa);
                    ffma2(acc[i][j], ab, wb);
                }
            }
        }
        __syncthreads();
    }
#pragma unroll
    for (int i = 0; i < 8; i++)
#pragma unroll
        for (int j = 0; j < 8; j++) {
            int m = m0 + ty + 16*i, n = n0 + tx + 16*j;
            C[(size_t)m * N + n] = acc[i][j].x + acc[i][j].y + bias[n];
        }
}

// ---------------------------------------------------------------------------
// proj GEMM writing bf16 hi/lo split (for q and k — fp32 never materialized)
// ---------------------------------------------------------------------------
__global__ void __launch_bounds__(256, 1)
proj_gemm_split(const float* __restrict__ A, const float* __restrict__ W,
                const float* __restrict__ bias,
                __nv_bfloat16* __restrict__ Chi, __nv_bfloat16* __restrict__ Clo) {
    const int K = DDIM, N = DDIM;
    __shared__ float As[128][20];
    __shared__ float Ws[128][20];
    const int tid = threadIdx.x;
    const int tx = tid & 15, ty = tid >> 4;
    const int m0 = blockIdx.y * 128, n0 = blockIdx.x * 128;

    float2 acc[8][8];
#pragma unroll
    for (int i = 0; i < 8; i++)
#pragma unroll
        for (int j = 0; j < 8; j++) acc[i][j] = make_float2(0.f, 0.f);

    float4 pa[2], pw[2];
#pragma unroll
    for (int it = 0; it < 2; it++) {
        int idx = tid + 256 * it, row = idx >> 2, q = (idx & 3) << 2;
        pa[it] = *(const float4*)&A[(size_t)(m0 + row) * K + q];
        pw[it] = *(const float4*)&W[(size_t)(n0 + row) * K + q];
    }
    for (int k0 = 0; k0 < K; k0 += 16) {
#pragma unroll
        for (int it = 0; it < 2; it++) {
            int idx = tid + 256 * it, row = idx >> 2, q = (idx & 3) << 2;
            *(float4*)&As[row][q] = pa[it];
            *(float4*)&Ws[row][q] = pw[it];
        }
        __syncthreads();
        if (k0 + 16 < K) {
#pragma unroll
            for (int it = 0; it < 2; it++) {
                int idx = tid + 256 * it, row = idx >> 2, q = (idx & 3) << 2;
                pa[it] = *(const float4*)&A[(size_t)(m0 + row) * K + k0 + 16 + q];
                pw[it] = *(const float4*)&W[(size_t)(n0 + row) * K + k0 + 16 + q];
            }
        }
#pragma unroll
        for (int kk0 = 0; kk0 < 16; kk0 += 4) {
            float4 af[8];
#pragma unroll
            for (int i = 0; i < 8; i++) af[i] = *(const float4*)&As[ty + 16*i][kk0];
#pragma unroll
            for (int j = 0; j < 8; j++) {
                float4 wf = *(const float4*)&Ws[tx + 16*j][kk0];
                float2 wa = make_float2(wf.x, wf.y), wb = make_float2(wf.z, wf.w);
#pragma unroll
                for (int i = 0; i < 8; i++) {
                    float2 aa = make_float2(af[i].x, af[i].y);
                    float2 ab = make_float2(af[i].z, af[i].w);
                    ffma2(acc[i][j], aa, wa);
                    ffma2(acc[i][j], ab, wb);
                }
            }
        }
        __syncthreads();
    }
#pragma unroll
    for (int i = 0; i < 8; i++)
#pragma unroll
        for (int j = 0; j < 8; j++) {
            int m = m0 + ty + 16*i, n = n0 + tx + 16*j;
            float v = acc[i][j].x + acc[i][j].y + bias[n];
            __nv_bfloat16 hi = __float2bfloat16(v);
            __nv_bfloat16 lo = __float2bfloat16(v - __bfloat162float(hi));
            Chi[(size_t)m * N + n] = hi;
            Clo[(size_t)m * N + n] = lo;
        }
}

// ---------------------------------------------------------------------------
// rel[r,n] = pos_emb[r]·Wp[n] + bp[n], written as bf16 hi/lo
// ---------------------------------------------------------------------------
__global__ void rel_proj(const float* __restrict__ pos_emb, const float* __restrict__ Wp,
                         const float* __restrict__ bp,
                         __nv_bfloat16* __restrict__ relhi, __nv_bfloat16* __restrict__ rello) {
    __shared__ float pe[DH];
    __shared__ float wps[DH][DH + 1];
    const int r = blockIdx.x;
    const int tid = threadIdx.x;
    pe[tid] = pos_emb[(size_t)r * DH + tid];
#pragma unroll
    for (int j = 0; j < DH; j++) wps[j][tid] = Wp[(size_t)j * DH + tid];
    __syncthreads();
    float acc = bp[tid];
#pragma unroll 8
    for (int k = 0; k < DH; k++) acc += pe[k] * wps[tid][k];
    __nv_bfloat16 hi = __float2bfloat16(acc);
    __nv_bfloat16 lo = __float2bfloat16(acc - __bfloat162float(hi));
    relhi[(size_t)r * DH + tid] = hi;
    rello[(size_t)r * DH + tid] = lo;
}

// ---------------------------------------------------------------------------
__global__ void softmax_kernel(const float* __restrict__ outc, const float* __restrict__ outp,
                               float* __restrict__ attn) {
    const size_t row = blockIdx.x;
    const float* c = outc + row * SS;
    const float* p = outp + row * SS;
    const int tid = threadIdx.x;
    const int lane = tid & 31, wid = tid >> 5;
    const float scale = 0.044194173824159216f; // 1/sqrt(512)

    float4 c4 = *(const float4*)&c[4 * tid];
    float4 p4 = *(const float4*)&p[4 * tid];
    float v[4];
    v[0] = (c4.x + p4.x) * scale; v[1] = (c4.y + p4.y) * scale;
    v[2] = (c4.z + p4.z) * scale; v[3] = (c4.w + p4.w) * scale;
    float m = fmaxf(fmaxf(v[0], v[1]), fmaxf(v[2], v[3]));
#pragma unroll
    for (int o = 16; o > 0; o >>= 1) m = fmaxf(m, __shfl_xor_sync(0xffffffffu, m, o));
    __shared__ float redm[8], reds[8];
    if (lane == 0) redm[wid] = m;
    __syncthreads();
    if (tid == 0) {
        float mm = redm[0];
#pragma unroll
        for (int i = 1; i < 8; i++) mm = fmaxf(mm, redm[i]);
        redm[0] = mm;
    }
    __syncthreads();
    m = redm[0];

    float s = 0.f;
#pragma unroll
    for (int u = 0; u < 4; u++) { v[u] = __expf(v[u] - m); s += v[u]; }
#pragma unroll
    for (int o = 16; o > 0; o >>= 1) s += __shfl_xor_sync(0xffffffffu, s, o);
    if (lane == 0) reds[wid] = s;
    __syncthreads();
    if (tid == 0) {
        float ss = 0.f;
#pragma unroll
        for (int i = 0; i < 8; i++) ss += reds[i];
        reds[0] = ss;
    }
    __syncthreads();
    const float inv = 1.f / reds[0];
    float4 o4 = make_float4(v[0] * inv, v[1] * inv, v[2] * inv, v[3] * inv);
    *(float4*)&attn[row * SS + 4 * tid] = o4;
}

// ---------------------------------------------------------------------------
__global__ void __launch_bounds__(256, 2)
av_kernel(const float* __restrict__ attn, const float* __restrict__ Vp,
          float* __restrict__ Oh) {
    extern __shared__ float sm[];
    float (*as_)[68] = (float(*)[68])sm;
    float (*vsT)[68] = (float(*)[68])(sm + 128 * 68);
    const int z = blockIdx.y;
    const int b = z >> 3, h = z & 7;
    const int s0 = blockIdx.x * 128;
    const int tid = threadIdx.x, tx = tid & 15, ty = tid >> 4;

    float2 acc[8][4];
#pragma unroll
    for (int i = 0; i < 8; i++)
#pragma unroll
        for (int j = 0; j < 4; j++) acc[i][j] = make_float2(0.f, 0.f);

    for (int t0 = 0; t0 < SS; t0 += 64) {
#pragma unroll
        for (int it = 0; it < 8; it++) {
            int idx = tid + 256 * it, row = idx >> 4, c = (idx & 15) << 2;
            *(float4*)&as_[row][c] =
                *(const float4*)&attn[((size_t)z * SS + s0 + row) * SS + t0 + c];
        }
#pragma unroll
        for (int it = 0; it < 4; it++) {
            int idx = tid + 256 * it;
            int trow = idx & 63, cb = (idx >> 6) << 2;
            float4 v4 = *(const float4*)&Vp[((size_t)(b * SS + t0 + trow)) * DDIM + h * DH + cb];
            vsT[cb + 0][trow] = v4.x;
            vsT[cb + 1][trow] = v4.y;
            vsT[cb + 2][trow] = v4.z;
            vsT[cb + 3][trow] = v4.w;
        }
        __syncthreads();
#pragma unroll 4
        for (int tt0 = 0; tt0 < 64; tt0 += 4) {
            float4 af[8];
#pragma unroll
            for (int i = 0; i < 8; i++) af[i] = *(const float4*)&as_[ty + 16*i][tt0];
#pragma unroll
            for (int j = 0; j < 4; j++) {
                float4 vf = *(const float4*)&vsT[tx + 16*j][tt0];
                float2 va = make_float2(vf.x, vf.y), vb = make_float2(vf.z, vf.w);
#pragma unroll
                for (int i = 0; i < 8; i++) {
                    float2 aa = make_float2(af[i].x, af[i].y);
                    float2 ab = make_float2(af[i].z, af[i].w);
                    ffma2(acc[i][j], aa, va);
                    ffma2(acc[i][j], ab, vb);
                }
            }
        }
        __syncthreads();
    }
#pragma unroll
    for (int i = 0; i < 8; i++)
#pragma unroll
        for (int j = 0; j < 4; j++)
            Oh[((size_t)(b * SS + s0 + ty + 16*i)) * DDIM + h * DH + tx + 16*j] =
                acc[i][j].x + acc[i][j].y;
}

// ---------------------------------------------------------------------------
extern "C" void kernel_launch(void* const* d_in, const int* in_sizes, int n_in,
                              void* d_out, int out_size) {
    const float* query   = (const float*)d_in[0];
    const float* key     = (const float*)d_in[1];
    const float* value   = (const float*)d_in[2];
    const float* pos_emb = (const float*)d_in[3];
    const float* Wq = (const float*)d_in[4];
    const float* bq = (const float*)d_in[5];
    const float* Wk = (const float*)d_in[6];
    const float* bk = (const float*)d_in[7];
    const float* Wv = (const float*)d_in[8];
    const float* bv = (const float*)d_in[9];
    const float* Wo = (const float*)d_in[10];
    const float* bo = (const float*)d_in[11];
    const float* Wp = (const float*)d_in[12];
    const float* bp = (const float*)d_in[13];
    float* out = (float*)d_out;

    __nv_bfloat16 *qhi, *qlo, *khi, *klo, *relhi, *rello;
    float *gv, *goh;
    cudaGetSymbolAddress((void**)&qhi, g_qhi);
    cudaGetSymbolAddress((void**)&qlo, g_qlo);
    cudaGetSymbolAddress((void**)&khi, g_khi);
    cudaGetSymbolAddress((void**)&klo, g_klo);
    cudaGetSymbolAddress((void**)&gv, g_v);
    cudaGetSymbolAddress((void**)&goh, g_oh);
    cudaGetSymbolAddress((void**)&relhi, g_relhi);
    cudaGetSymbolAddress((void**)&rello, g_rello);

    const int av_smem = (128 + 64) * 68 * (int)sizeof(float);
    cudaFuncSetAttribute(content_kernel, cudaFuncAttributeMaxDynamicSharedMemorySize, T_SMEM_TOTAL);
    cudaFuncSetAttribute(pos_mma_kernel, cudaFuncAttributeMaxDynamicSharedMemorySize, T_SMEM_TOTAL);
    cudaFuncSetAttribute(av_kernel,      cudaFuncAttributeMaxDynamicSharedMemorySize, av_smem);

    dim3 gproj(DDIM / 128, (BB * SS) / 128);   // (4, 32)
    proj_gemm_split<<<gproj, 256>>>(query, Wq, bq, qhi, qlo);           // 0
    rel_proj<<<RP, DH>>>(pos_emb, Wp, bp, relhi, rello);                // 1
    proj_gemm_split<<<gproj, 256>>>(key, Wk, bk, khi, klo);             // 2
    pos_mma_kernel<<<dim3(9, SS / 128, BB * HH), 256, T_SMEM_TOTAL>>>(
        qhi, qlo, relhi, rello, out + OFF_POS);                         // 3 (ncu slot)
    content_kernel<<<dim3(SS / 128, SS / 128, BB * HH), 256, T_SMEM_TOTAL>>>(
        qhi, qlo, khi, klo, out + OFF_CONTENT);                         // 4
    proj_gemm<<<gproj, 256>>>(value, Wv, bv, gv);                       // 5
    softmax_kernel<<<BB * HH * SS, 256>>>(out + OFF_CONTENT, out + OFF_POS, out + OFF_ATTN); // 6
    av_kernel<<<dim3(SS / 128, BB * HH), 256, av_smem>>>(out + OFF_ATTN, gv, goh);           // 7
    proj_gemm<<<gproj, 256>>>(goh, Wo, bo, out);                        // 8
}